// round 4
// baseline (speedup 1.0000x reference)
#include <cuda_runtime.h>
#include <cuda_bf16.h>
#include <cstdint>

// Problem constants
#define Z   16
#define Y   384
#define X   384
#define NVOX (Z*Y*X)              // 2,359,296
#define PZ  18                     // padded z
#define PY  386                    // padded y
#define PXW 396                    // padded row width (>= 386, mult of 4, room for 8-cell groups)
#define ZP  17                     // z-pairs
#define CX  385                    // cells per row (and cell rows per pair)
#define GRP 49                     // ceil(385/8) x-groups of 8 cells
#define NCELLT (ZP*CX*GRP)         // 320,705 threads in pass B
#define EPSF 1e-12f

// Scratch: zero-initialized at module load; padding is never written, so it
// stays zero forever. Interior is fully rewritten each launch (deterministic).
__device__ __align__(16) float         g_w [PZ*PY*PXW];
__device__ __align__(16) unsigned char g_cb[PZ*PY*PXW];
__device__ double g_acc[3];   // [0]=sum pw*la, [1]=sum la+pa, [2]=sum interior bce

__global__ void k_init() {
    g_acc[0] = 0.0; g_acc[1] = 0.0; g_acc[2] = 0.0;
}

// Pass A: per-voxel sigmoid -> w = (l ? s-1 : s), cb = l | (s>0.5)<<1
__global__ void k_voxel(const float* __restrict__ pred, const int* __restrict__ lab) {
    int i4 = blockIdx.x * blockDim.x + threadIdx.x;
    if (i4 >= NVOX / 4) return;
    int i = i4 * 4;
    int x = i % X;
    int r = i / X;          // z*Y + y
    int y = r % Y;
    int z = r / Y;

    float4 p = *(const float4*)(pred + i);
    int4   l = *(const int4*)(lab + i);

    float pv[4] = {p.x, p.y, p.z, p.w};
    int   lv[4] = {l.x, l.y, l.z, l.w};

    int pbase = ((z + 1) * PY + (y + 1)) * PXW + (x + 1);
#pragma unroll
    for (int j = 0; j < 4; j++) {
        float u = __expf(-pv[j]);
        float s = __fdividef(1.0f, 1.0f + u);
        float w = lv[j] ? (s - 1.0f) : s;       // (s-l); sign encodes l
        int   pb = (s > 0.5f) ? 1 : 0;
        g_w [pbase + j] = w;
        g_cb[pbase + j] = (unsigned char)(lv[j] | (pb << 1));
    }
}

// Pass B: each thread handles 8 consecutive cells along x for one (zpair, y).
__global__ void __launch_bounds__(256) k_cells(const float* __restrict__ area) {
    __shared__ float sA[256];
    __shared__ float rN[8], rD[8], rB[8];

    sA[threadIdx.x] = area[threadIdx.x];   // blockDim == 256
    __syncthreads();

    int t = blockIdx.x * blockDim.x + threadIdx.x;
    float accN = 0.0f, accD = 0.0f, accB = 0.0f;

    if (t < NCELLT) {
        int xg = t % GRP;
        int r  = t / GRP;
        int y  = r % CX;
        int zp = r / CX;
        int px0 = xg * 8;

        float    wv[4][9];
        unsigned cA[4], cB4[4];
        unsigned char cl[4];
#pragma unroll
        for (int rr = 0; rr < 4; rr++) {
            int dz = rr >> 1, dy = rr & 1;
            int base = ((zp + dz) * PY + (y + dy)) * PXW + px0;
            float4 a = *(const float4*)(g_w + base);
            float4 b = *(const float4*)(g_w + base + 4);
            wv[rr][0] = a.x; wv[rr][1] = a.y; wv[rr][2] = a.z; wv[rr][3] = a.w;
            wv[rr][4] = b.x; wv[rr][5] = b.y; wv[rr][6] = b.z; wv[rr][7] = b.w;
            wv[rr][8] = g_w[base + 8];
            cA[rr]  = *(const unsigned*)(g_cb + base);
            cB4[rr] = *(const unsigned*)(g_cb + base + 4);
            cl[rr]  = g_cb[base + 8];
        }

        // byte-SIMD column codes: per byte c, bits {2r, 2r+1} = (l_r, p_r)
        unsigned mA = cA[0]  | (cA[1]  << 2) | (cA[2]  << 4) | (cA[3]  << 6);
        unsigned mB = cB4[0] | (cB4[1] << 2) | (cB4[2] << 4) | (cB4[3] << 6);

        int colc[9];
#pragma unroll
        for (int c = 0; c < 4; c++) colc[c]     = (mA >> (8 * c)) & 0xFF;
#pragma unroll
        for (int c = 0; c < 4; c++) colc[c + 4] = (mB >> (8 * c)) & 0xFF;
        colc[8] = (int)cl[0] | ((int)cl[1] << 2) | ((int)cl[2] << 4) | ((int)cl[3] << 6);

        // separable per-column squared sums
        float cd2[9];
#pragma unroll
        for (int c = 0; c < 9; c++) {
            float s0 = wv[0][c], s1 = wv[1][c], s2 = wv[2][c], s3 = wv[3][c];
            cd2[c] = fmaf(s0, s0, fmaf(s1, s1, fmaf(s2, s2, s3 * s3)));
        }

        int nvalid = CX - px0;   // cells valid: c < nvalid
#pragma unroll
        for (int c = 0; c < 8; c++) {
            if (c < nvalid) {
                int cp = colc[c], cn = colc[c + 1];
                int code  = (cp & 0x55) | ((cn & 0x55) << 1);   // label byte
                int pcode = ((cp & 0xAA) >> 1) | (cn & 0xAA);   // pred byte
                float d2 = cd2[c] + cd2[c + 1];
                float la = sA[code];
                float pa = sA[pcode];
                accN = fmaf(fmaf(d2, -0.125f, 1.0f), la, accN); // pw * label_area
                accD += la + pa;
                if (code == 0 || code == 255) {
                    // bce per corner: -log(max(1-|w|, EPS))  (covers both label cases)
                    float b = 0.0f;
#pragma unroll
                    for (int rr = 0; rr < 4; rr++) {
                        b += __logf(fmaxf(1.0f - fabsf(wv[rr][c]),     EPSF));
                        b += __logf(fmaxf(1.0f - fabsf(wv[rr][c + 1]), EPSF));
                    }
                    accB -= b;
                }
            }
        }
    }

    // block reduction -> double atomics
#pragma unroll
    for (int o = 16; o > 0; o >>= 1) {
        accN += __shfl_down_sync(0xffffffffu, accN, o);
        accD += __shfl_down_sync(0xffffffffu, accD, o);
        accB += __shfl_down_sync(0xffffffffu, accB, o);
    }
    int wid = threadIdx.x >> 5, lane = threadIdx.x & 31;
    if (lane == 0) { rN[wid] = accN; rD[wid] = accD; rB[wid] = accB; }
    __syncthreads();
    if (threadIdx.x == 0) {
        float n = 0.0f, d = 0.0f, b = 0.0f;
#pragma unroll
        for (int i = 0; i < 8; i++) { n += rN[i]; d += rD[i]; b += rB[i]; }
        atomicAdd(&g_acc[0], (double)n);
        atomicAdd(&g_acc[1], (double)d);
        atomicAdd(&g_acc[2], (double)b);
    }
}

__global__ void k_fin(float* __restrict__ out) {
    double num = 2.0 * g_acc[0];
    double den = g_acc[1];
    double vol = g_acc[2] / (8.0 * (double)CX * (double)CX);
    double dice = 1.0 - (num + 1e-3) / (den + 1e-3);
    out[0] = (float)(dice + vol);
}

extern "C" void kernel_launch(void* const* d_in, const int* in_sizes, int n_in,
                              void* d_out, int out_size) {
    const float* pred = (const float*)d_in[0];
    const int*   lab  = (const int*)d_in[1];
    const float* area = (const float*)d_in[2];
    (void)in_sizes; (void)n_in; (void)out_size;

    k_init<<<1, 1>>>();
    k_voxel<<<(NVOX / 4 + 255) / 256, 256>>>(pred, lab);
    k_cells<<<(NCELLT + 255) / 256, 256>>>(area);
    k_fin<<<1, 1>>>((float*)d_out);
}